// round 15
// baseline (speedup 1.0000x reference)
#include <cuda_runtime.h>
#include <math.h>

// Capacity bounds for static scratch (actual dims derived at runtime).
#define MAX_N  150000
#define MAX_E  2400000
#define MAX_HC 96
#define MAX_C  48
#define MAX_H  4
#define MAX_G  512

#define CAP_NHC ((long long)MAX_N * MAX_HC)
#define CAP_NC  ((long long)MAX_N * MAX_C)
#define CAP_EH  ((long long)MAX_E * MAX_H)
#define CAP_E   ((long long)MAX_E)
#define CAP_NH  ((long long)MAX_N * MAX_H)
#define CAP_N   ((long long)MAX_N)
#define CAP_GC  ((long long)MAX_G * MAX_C)
#define CAP_G   ((long long)MAX_G)

// ---------------- static scratch (no allocation allowed) ----------------
// Only ever accessed through pointers from cudaGetSymbolAddress (GB300 ATS
// silently dereferences the host shadow if you pass the symbol as an arg!).
__device__ float g_xl1[CAP_NHC];
__device__ float g_xr1[CAP_NHC];
__device__ float g_O1 [CAP_NHC];     // fallback path only
__device__ float g_h1 [CAP_NHC];
__device__ float g_ex1[CAP_EH];      // fallback path only
__device__ float g_d1 [CAP_NH];      // fallback path only

__device__ float g_xl2[CAP_NC];
__device__ float g_xr2[CAP_NC];
__device__ float g_O2 [CAP_NC];      // fallback path only
__device__ float g_h2 [CAP_NC];      // fallback path only
__device__ float g_ex2[CAP_E];       // fallback path only
__device__ float g_d2 [CAP_N];       // fallback path only

__device__ float g_tmp [CAP_NC];
__device__ float g_gate[CAP_N];
__device__ float g_gd  [CAP_G];
__device__ float g_pool[CAP_GC];

// CSR scratch
__device__ int g_counts[CAP_N];
__device__ int g_rowptr[CAP_N + 1];
__device__ int g_cursor[CAP_N];
__device__ int g_colsrc[CAP_E];
__device__ int g_bsum[256];
__device__ int g_gbar[4];            // software grid-barrier counters

__device__ __forceinline__ float lrelu(float v) { return v > 0.f ? v : 0.2f * v; }

// ---- packed f32x2 helpers (Blackwell FFMA2; ptxas won't emit from C++) ----
__device__ __forceinline__ unsigned long long pack2(float x, float y) {
    unsigned long long r;
    asm("mov.b64 %0, {%1, %2};" : "=l"(r) : "f"(x), "f"(y));
    return r;
}
__device__ __forceinline__ void fma2(unsigned long long& d,
                                     unsigned long long a, unsigned long long b) {
    asm("fma.rn.f32x2 %0, %1, %2, %0;" : "+l"(d) : "l"(a), "l"(b));
}
__device__ __forceinline__ float2 unpack2(unsigned long long v) {
    float2 r;
    asm("mov.b64 {%0, %1}, %2;" : "=f"(r.x), "=f"(r.y) : "l"(v));
    return r;
}

// ---- software grid barrier (all blocks co-resident by construction) ----
__device__ __forceinline__ void gbar(int* bar, int expected) {
    __syncthreads();
    if (threadIdx.x == 0) {
        __threadfence();
        atomicAdd(bar, 1);
        while (*(volatile int*)bar < expected) { }
        __threadfence();
    }
    __syncthreads();
}

// ---------------- init (fallback path only) ----------------
__global__ void k_init(int* counts, float* gd, float* pool,
                       float* O1, float* O2, float* d1, float* d2,
                       int N, int G, int HC1, int C, int H) {
    long long tot = (long long)N * HC1;
    long long stride = (long long)gridDim.x * blockDim.x;
    for (long long i = (long long)blockIdx.x * blockDim.x + threadIdx.x;
         i < tot; i += stride) {
        O1[i] = 0.f;
        if (i < (long long)N * C) O2[i] = 0.f;
        if (i < (long long)N * H) d1[i] = 0.f;
        if (i < N)                { d2[i] = 0.f; counts[i] = 0; }
        if (i < (long long)G * C) pool[i] = 0.f;
        if (i < G)                gd[i] = 0.f;
    }
}

// ---------------- MEGA CSR: init + count + scan, one launch ----------------
__global__ void k_csr_mega(const int* __restrict__ dst,
                           int* __restrict__ counts, int* __restrict__ rowptr,
                           int* __restrict__ cursor, int* __restrict__ bsum,
                           float* __restrict__ gd, float* __restrict__ pool,
                           int* __restrict__ bar,
                           int Nn, int E, int G, int C) {
    const int nb = gridDim.x;                 // 256
    const int t = threadIdx.x;
    const int bid = blockIdx.x;
    const int gtid = bid * 256 + t;
    const int gstride = nb * 256;

    // ---- phase 0: zero counts + gd + pool ----
    for (int i = gtid; i < Nn; i += gstride) counts[i] = 0;
    if (bid == 0) {
        for (int i = t; i < G * C; i += 256) pool[i] = 0.f;
        for (int i = t; i < G; i += 256) gd[i] = 0.f;
    }
    gbar(&bar[0], nb);

    // ---- phase 1: histogram (ILP-4 int4 when aligned) ----
    if ((E & 3) == 0) {
        int E4 = E >> 2;
        for (int i = gtid; i < E4; i += gstride) {
            int4 v = __ldg(&((const int4*)dst)[i]);
            atomicAdd(&counts[v.x], 1);
            atomicAdd(&counts[v.y], 1);
            atomicAdd(&counts[v.z], 1);
            atomicAdd(&counts[v.w], 1);
        }
    } else {
        for (int e = gtid; e < E; e += gstride)
            atomicAdd(&counts[dst[e]], 1);
    }
    gbar(&bar[1], nb);

    // ---- phase 2: per-block sums over contiguous chunk ----
    __shared__ int sh[256];
    __shared__ int sb[256];
    const int chunk = (Nn + nb - 1) / nb;
    {
        int beg = bid * chunk;
        int end = min(beg + chunk, Nn);
        int s = 0;
        for (int i = beg + t; i < end; i += 256) s += counts[i];
        sh[t] = s;
        __syncthreads();
        for (int d = 128; d; d >>= 1) {
            if (t < d) sh[t] += sh[t + d];
            __syncthreads();
        }
        if (t == 0) bsum[bid] = sh[0];
    }
    gbar(&bar[2], nb);

    // ---- phase 3: cross-block scan + local exclusive scan + write ----
    sb[t] = bsum[t];
    __syncthreads();
    for (int d = 1; d < 256; d <<= 1) {
        int v = (t >= d) ? sb[t - d] : 0;
        __syncthreads();
        sb[t] += v;
        __syncthreads();
    }
    int blockoff = (bid == 0) ? 0 : sb[bid - 1];

    int bbeg = bid * chunk;
    int bend = min(bbeg + chunk, Nn);
    int tchunk = (chunk + 255) / 256;
    int tb = bbeg + t * tchunk;
    int te = min(tb + tchunk, bend);
    int s = 0;
    for (int i = tb; i < te; i++) s += counts[i];
    int orig = s;
    sh[t] = s;
    __syncthreads();
    for (int d = 1; d < 256; d <<= 1) {
        int v = (t >= d) ? sh[t - d] : 0;
        __syncthreads();
        sh[t] += v;
        __syncthreads();
    }
    int off = blockoff + sh[t] - orig;
    for (int i = tb; i < te; i++) {
        rowptr[i] = off;
        cursor[i] = off;
        off += counts[i];
    }
    if (bid == nb - 1 && t == 255) rowptr[Nn] = E;
}

// ---------------- FUSED: GEMM1 (FFMA2, prepacked W) + ILP-8 CSR fill -------
template <int K>
__global__ void k_gemm1_fill(const float* __restrict__ X,
                             const float* __restrict__ Wl, const float* __restrict__ Wr,
                             float* __restrict__ Yl, float* __restrict__ Yr, int n,
                             int gemmBlocks,
                             const int* __restrict__ src, const int* __restrict__ dst,
                             int* __restrict__ cursor, int* __restrict__ colsrc, int E) {
    constexpr int J = 64;
    constexpr int NPW = 4;
    constexpr int XR = K / 32;
    __shared__ float2 WsLP[K * 32];   // packed (W[k][c], W[k][c+32])
    __shared__ float2 WsRP[K * 32];

    int tid = threadIdx.x;

    if (blockIdx.x >= gemmBlocks) {
        // ---- fill role (ILP-8) ----
        int i = (blockIdx.x - gemmBlocks) * blockDim.x + tid;
        int E8 = E >> 3;
        if (i < E8) {
            int4 da = __ldg(&((const int4*)dst)[2 * i]);
            int4 db = __ldg(&((const int4*)dst)[2 * i + 1]);
            int4 sa = __ldg(&((const int4*)src)[2 * i]);
            int4 sb = __ldg(&((const int4*)src)[2 * i + 1]);
            int p0 = atomicAdd(&cursor[da.x], 1);
            int p1 = atomicAdd(&cursor[da.y], 1);
            int p2 = atomicAdd(&cursor[da.z], 1);
            int p3 = atomicAdd(&cursor[da.w], 1);
            int p4 = atomicAdd(&cursor[db.x], 1);
            int p5 = atomicAdd(&cursor[db.y], 1);
            int p6 = atomicAdd(&cursor[db.z], 1);
            int p7 = atomicAdd(&cursor[db.w], 1);
            colsrc[p0] = sa.x; colsrc[p1] = sa.y; colsrc[p2] = sa.z; colsrc[p3] = sa.w;
            colsrc[p4] = sb.x; colsrc[p5] = sb.y; colsrc[p6] = sb.z; colsrc[p7] = sb.w;
        }
        if (i < (E & 7)) {
            int e = (E8 << 3) + i;
            int pos = atomicAdd(&cursor[dst[e]], 1);
            colsrc[pos] = src[e];
        }
        return;
    }

    // ---- GEMM role (R10-proven: x in registers, shfl broadcast) ----
    for (int l = tid; l < K * 32; l += 256) {
        int k = l >> 5, c = l & 31;
        WsLP[l] = make_float2(Wl[k * J + c], Wl[k * J + 32 + c]);
        WsRP[l] = make_float2(Wr[k * J + c], Wr[k * J + 32 + c]);
    }
    __syncthreads();

    int warp = tid >> 5, lane = tid & 31;
    int base = (blockIdx.x * 8 + warp) * NPW;
    if (base >= n) return;

    float xreg[NPW][XR];
#pragma unroll
    for (int p = 0; p < NPW; p++) {
        int node = base + p;
        bool ok = node < n;
#pragma unroll
        for (int i = 0; i < XR; i++)
            xreg[p][i] = ok ? X[(size_t)node * K + i * 32 + lane] : 0.f;
    }

    unsigned long long aL[NPW], aR[NPW];
#pragma unroll
    for (int p = 0; p < NPW; p++) { aL[p] = pack2(0.f, 0.f); aR[p] = pack2(0.f, 0.f); }

    const unsigned long long* WL = (const unsigned long long*)WsLP;
    const unsigned long long* WR = (const unsigned long long*)WsRP;
#pragma unroll
    for (int ko = 0; ko < XR; ko++) {
#pragma unroll
        for (int ki = 0; ki < 32; ki++) {
            int k = ko * 32 + ki;
            unsigned long long wlp = WL[k * 32 + lane];
            unsigned long long wrp = WR[k * 32 + lane];
#pragma unroll
            for (int p = 0; p < NPW; p++) {
                float xk = __shfl_sync(0xffffffffu, xreg[p][ko], ki);
                unsigned long long xkp = pack2(xk, xk);
                fma2(aL[p], xkp, wlp);
                fma2(aR[p], xkp, wrp);
            }
        }
    }
#pragma unroll
    for (int p = 0; p < NPW; p++) {
        int node = base + p;
        if (node < n) {
            float2 l2 = unpack2(aL[p]), r2 = unpack2(aR[p]);
            Yl[(size_t)node * J + lane]      = l2.x;
            Yl[(size_t)node * J + 32 + lane] = l2.y;
            Yr[(size_t)node * J + lane]      = r2.x;
            Yr[(size_t)node * J + 32 + lane] = r2.y;
        }
    }
}

// ---------------- DUAL GEMM layer 2: FFMA2 {L,R}-prepacked, J=32, NPW=8 ----
// ncu R14: L1tex 79.9%, fma 26% at NPW=4 — crossbar-bound. NPW=8 halves the
// LDS.64 traffic per FMA (1 LDS.64 feeds 8 nodes), moving work to the idle
// SHFL/FMA pipes.
template <int K>
__global__ void k_gemm_dual32(const float* __restrict__ X,
                              const float* __restrict__ Wl, const float* __restrict__ Wr,
                              float* __restrict__ Yl, float* __restrict__ Yr, int n) {
    constexpr int J = 32;
    constexpr int NPW = 8;
    constexpr int XR = K / 32;
    __shared__ float2 WsP[K * 32];    // packed (Wl[k][c], Wr[k][c])
    int tid = threadIdx.x;
    for (int l = tid; l < K * 32; l += 256) {
        int k = l >> 5, c = l & 31;
        WsP[l] = make_float2(Wl[k * J + c], Wr[k * J + c]);
    }
    __syncthreads();

    int warp = tid >> 5, lane = tid & 31;
    int base = (blockIdx.x * 8 + warp) * NPW;
    if (base >= n) return;

    float xreg[NPW][XR];
#pragma unroll
    for (int p = 0; p < NPW; p++) {
        int node = base + p;
        bool ok = node < n;
#pragma unroll
        for (int i = 0; i < XR; i++)
            xreg[p][i] = ok ? X[(size_t)node * K + i * 32 + lane] : 0.f;
    }

    unsigned long long a[NPW];   // packed {accL, accR}
#pragma unroll
    for (int p = 0; p < NPW; p++) a[p] = pack2(0.f, 0.f);

    const unsigned long long* WP = (const unsigned long long*)WsP;
#pragma unroll
    for (int ko = 0; ko < XR; ko++) {
#pragma unroll
        for (int ki = 0; ki < 32; ki++) {
            int k = ko * 32 + ki;
            unsigned long long wp = WP[k * 32 + lane];
#pragma unroll
            for (int p = 0; p < NPW; p++) {
                float xk = __shfl_sync(0xffffffffu, xreg[p][ko], ki);
                fma2(a[p], pack2(xk, xk), wp);
            }
        }
    }
#pragma unroll
    for (int p = 0; p < NPW; p++) {
        int node = base + p;
        if (node < n) {
            float2 lr = unpack2(a[p]);
            Yl[(size_t)node * J + lane] = lr.x;
            Yr[(size_t)node * J + lane] = lr.y;
        }
    }
}

// ---------------- generic GEMM (fallback): Y = X@W (+bias, relu) -----------
__global__ void k_gemm(const float* __restrict__ X, const float* __restrict__ W,
                       const float* __restrict__ bias, float* __restrict__ Y,
                       int n, int K, int J, int do_relu) {
    int total = n * J;
    for (int idx = blockIdx.x * blockDim.x + threadIdx.x; idx < total;
         idx += gridDim.x * blockDim.x) {
        int r = idx / J;
        int j = idx - r * J;
        const float* xrow = X + (size_t)r * K;
        float acc = 0.f;
        int k = 0;
        for (; k + 4 <= K; k += 4) {
            acc += xrow[k]     * __ldg(&W[(k)     * J + j]);
            acc += xrow[k + 1] * __ldg(&W[(k + 1) * J + j]);
            acc += xrow[k + 2] * __ldg(&W[(k + 2) * J + j]);
            acc += xrow[k + 3] * __ldg(&W[(k + 3) * J + j]);
        }
        for (; k < K; k++) acc += xrow[k] * __ldg(&W[k * J + j]);
        if (bias) acc += __ldg(&bias[j]);
        if (do_relu) acc = fmaxf(acc, 0.f);
        Y[idx] = acc;
    }
}

// ---------------- FAST PATH layer 1: fused GATv2, float2, H=2, unroll-2 ----
__global__ void k_gat_fused2_h2(const int* __restrict__ rowptr, const int* __restrict__ colsrc,
                                const float* __restrict__ xl, const float* __restrict__ xr,
                                const float* __restrict__ att, const float* __restrict__ bias,
                                float* __restrict__ hout, int Nn) {
    int n = (blockIdx.x * blockDim.x + threadIdx.x) >> 5;
    int lane = threadIdx.x & 31;
    if (n >= Nn) return;

    const float2* xl2 = (const float2*)xl;
    float2 xrr = ((const float2*)xr)[(size_t)n * 32 + lane];
    float2 av  = __ldg(&((const float2*)att)[lane]);
    float accx = 0.f, accy = 0.f, den = 0.f;

    int beg = rowptr[n], end = rowptr[n + 1];
    int i = beg;
    for (; i + 1 < end; i += 2) {
        int s0 = __ldg(&colsrc[i]);
        int s1 = __ldg(&colsrc[i + 1]);
        float2 v0 = __ldg(&xl2[(size_t)s0 * 32 + lane]);
        float2 v1 = __ldg(&xl2[(size_t)s1 * 32 + lane]);
        float sc0 = lrelu(v0.x + xrr.x) * av.x + lrelu(v0.y + xrr.y) * av.y;
        float sc1 = lrelu(v1.x + xrr.x) * av.x + lrelu(v1.y + xrr.y) * av.y;
        sc0 += __shfl_xor_sync(0xffffffffu, sc0, 8);
        sc1 += __shfl_xor_sync(0xffffffffu, sc1, 8);
        sc0 += __shfl_xor_sync(0xffffffffu, sc0, 4);
        sc1 += __shfl_xor_sync(0xffffffffu, sc1, 4);
        sc0 += __shfl_xor_sync(0xffffffffu, sc0, 2);
        sc1 += __shfl_xor_sync(0xffffffffu, sc1, 2);
        sc0 += __shfl_xor_sync(0xffffffffu, sc0, 1);
        sc1 += __shfl_xor_sync(0xffffffffu, sc1, 1);
        float a0 = __expf(sc0), a1 = __expf(sc1);
        den += a0 + a1;
        accx = fmaf(a0, v0.x, accx); accx = fmaf(a1, v1.x, accx);
        accy = fmaf(a0, v0.y, accy); accy = fmaf(a1, v1.y, accy);
    }
    if (i < end) {
        int s = __ldg(&colsrc[i]);
        float2 v = __ldg(&xl2[(size_t)s * 32 + lane]);
        float sc = lrelu(v.x + xrr.x) * av.x + lrelu(v.y + xrr.y) * av.y;
        sc += __shfl_xor_sync(0xffffffffu, sc, 8);
        sc += __shfl_xor_sync(0xffffffffu, sc, 4);
        sc += __shfl_xor_sync(0xffffffffu, sc, 2);
        sc += __shfl_xor_sync(0xffffffffu, sc, 1);
        float a = __expf(sc);
        den += a;
        accx = fmaf(a, v.x, accx);
        accy = fmaf(a, v.y, accy);
    }
    float2 bv = __ldg(&((const float2*)bias)[lane]);
    float inv = (den > 0.f) ? 1.f / den : 0.f;
    float2 o;
    o.x = fmaxf(accx * inv + bv.x, 0.f);
    o.y = fmaxf(accy * inv + bv.y, 0.f);
    ((float2*)hout)[(size_t)n * 32 + lane] = o;
}

// ---------------- FAST PATH layer 2 + gate + pool, all fused, unroll-2 -----
__global__ void k_gat2_gate_pool(const int* __restrict__ rowptr, const int* __restrict__ colsrc,
                                 const float* __restrict__ xl, const float* __restrict__ xr,
                                 const float* __restrict__ att, const float* __restrict__ bias,
                                 const float* __restrict__ g1w, const float* __restrict__ g1b,
                                 const float* __restrict__ g2w, const float* __restrict__ g2b,
                                 const int* __restrict__ batch,
                                 float* __restrict__ gd, float* __restrict__ pool, int Nn) {
    int n = (blockIdx.x * blockDim.x + threadIdx.x) >> 5;
    int lane = threadIdx.x & 31;
    if (n >= Nn) return;
    int hw = lane >> 4;
    int l16 = lane & 15;
    unsigned hmask = hw ? 0xffff0000u : 0x0000ffffu;

    const float2* xl2 = (const float2*)xl;
    float2 xrr = ((const float2*)xr)[(size_t)n * 16 + l16];
    float2 av  = __ldg(&((const float2*)att)[l16]);
    float accx = 0.f, accy = 0.f, den = 0.f;

    int beg = rowptr[n], end = rowptr[n + 1];
    int i = beg + hw;
    for (; i + 2 < end; i += 4) {
        int s0 = __ldg(&colsrc[i]);
        int s1 = __ldg(&colsrc[i + 2]);
        float2 v0 = __ldg(&xl2[(size_t)s0 * 16 + l16]);
        float2 v1 = __ldg(&xl2[(size_t)s1 * 16 + l16]);
        float sc0 = lrelu(v0.x + xrr.x) * av.x + lrelu(v0.y + xrr.y) * av.y;
        float sc1 = lrelu(v1.x + xrr.x) * av.x + lrelu(v1.y + xrr.y) * av.y;
        sc0 += __shfl_xor_sync(hmask, sc0, 8);
        sc1 += __shfl_xor_sync(hmask, sc1, 8);
        sc0 += __shfl_xor_sync(hmask, sc0, 4);
        sc1 += __shfl_xor_sync(hmask, sc1, 4);
        sc0 += __shfl_xor_sync(hmask, sc0, 2);
        sc1 += __shfl_xor_sync(hmask, sc1, 2);
        sc0 += __shfl_xor_sync(hmask, sc0, 1);
        sc1 += __shfl_xor_sync(hmask, sc1, 1);
        float a0 = __expf(sc0), a1 = __expf(sc1);
        den += a0 + a1;
        accx = fmaf(a0, v0.x, accx); accx = fmaf(a1, v1.x, accx);
        accy = fmaf(a0, v0.y, accy); accy = fmaf(a1, v1.y, accy);
    }
    if (i < end) {
        int s = __ldg(&colsrc[i]);
        float2 v = __ldg(&xl2[(size_t)s * 16 + l16]);
        float sc = lrelu(v.x + xrr.x) * av.x + lrelu(v.y + xrr.y) * av.y;
        sc += __shfl_xor_sync(hmask, sc, 8);
        sc += __shfl_xor_sync(hmask, sc, 4);
        sc += __shfl_xor_sync(hmask, sc, 2);
        sc += __shfl_xor_sync(hmask, sc, 1);
        float a = __expf(sc);
        den += a;
        accx = fmaf(a, v.x, accx);
        accy = fmaf(a, v.y, accy);
    }
    den  += __shfl_xor_sync(0xffffffffu, den, 16);
    accx += __shfl_xor_sync(0xffffffffu, accx, 16);
    accy += __shfl_xor_sync(0xffffffffu, accy, 16);
    float2 bv = __ldg(&((const float2*)bias)[l16]);
    float inv = (den > 0.f) ? 1.f / den : 0.f;
    float2 o;
    o.x = fmaxf(accx * inv + bv.x, 0.f);
    o.y = fmaxf(accy * inv + bv.y, 0.f);

    // gate MLP: lane j computes t[j] = relu(sum_k h[k]*g1w[k][j] + g1b[j])
    float t = __ldg(&g1b[lane]);
#pragma unroll
    for (int k = 0; k < 32; k += 2) {
        float hx = __shfl_sync(0xffffffffu, o.x, k >> 1);
        float hy = __shfl_sync(0xffffffffu, o.y, k >> 1);
        t = fmaf(hx, __ldg(&g1w[k * 32 + lane]), t);
        t = fmaf(hy, __ldg(&g1w[(k + 1) * 32 + lane]), t);
    }
    t = fmaxf(t, 0.f);
    float y = t * __ldg(&g2w[lane]);
#pragma unroll
    for (int of = 16; of; of >>= 1) y += __shfl_xor_sync(0xffffffffu, y, of);
    float ge = __expf(y + __ldg(&g2b[0]));

    float ax = __shfl_sync(0xffffffffu, o.x, lane >> 1);
    float ay = __shfl_sync(0xffffffffu, o.y, lane >> 1);
    float hj = (lane & 1) ? ay : ax;
    int b = batch[n];
    atomicAdd(&pool[(size_t)b * 32 + lane], ge * hj);
    if (lane == 0) atomicAdd(&gd[b], ge);
}

// ---------------- FALLBACK: edge kernels (any shape) ----------------
__global__ void k_score(const int* __restrict__ src, const int* __restrict__ dst,
                        const float* __restrict__ xl, const float* __restrict__ xr,
                        const float* __restrict__ att, float* __restrict__ ex,
                        float* __restrict__ den, int E, int H, int C, int HC) {
    int e = (blockIdx.x * blockDim.x + threadIdx.x) >> 5;
    int lane = threadIdx.x & 31;
    if (e >= E) return;
    int s = src[e], d = dst[e];
    for (int h = 0; h < H; h++) {
        float acc = 0.f;
        for (int c = lane; c < C; c += 32) {
            float v = xl[(size_t)s * HC + h * C + c] + xr[(size_t)d * HC + h * C + c];
            acc += lrelu(v) * __ldg(&att[h * C + c]);
        }
#pragma unroll
        for (int o = 16; o; o >>= 1) acc += __shfl_xor_sync(0xffffffffu, acc, o);
        if (lane == 0) {
            float t = expf(acc);
            ex[(size_t)e * H + h] = t;
            atomicAdd(&den[d * H + h], t);
        }
    }
}

__global__ void k_agg(const int* __restrict__ src, const int* __restrict__ dst,
                      const float* __restrict__ xl, const float* __restrict__ ex,
                      const float* __restrict__ den, float* __restrict__ O,
                      int E, int H, int C, int HC) {
    int e = (blockIdx.x * blockDim.x + threadIdx.x) >> 5;
    int lane = threadIdx.x & 31;
    if (e >= E) return;
    int s = src[e], d = dst[e];
    for (int h = 0; h < H; h++) {
        float alpha = ex[(size_t)e * H + h] / den[d * H + h];
        for (int c = lane; c < C; c += 32)
            atomicAdd(&O[(size_t)d * HC + h * C + c],
                      alpha * xl[(size_t)s * HC + h * C + c]);
    }
}

__global__ void k_relu_bias(const float* __restrict__ O, const float* __restrict__ b,
                            float* __restrict__ hout, int total, int HC) {
    for (int i = blockIdx.x * blockDim.x + threadIdx.x; i < total;
         i += gridDim.x * blockDim.x) {
        int col = i % HC;
        hout[i] = fmaxf(O[i] + __ldg(&b[col]), 0.f);
    }
}

__global__ void k_gate2(const float* __restrict__ tmp, const float* __restrict__ g2w,
                        const float* __restrict__ g2b, const int* __restrict__ batch,
                        float* __restrict__ gate, float* __restrict__ gd, int N, int C) {
    int n = (blockIdx.x * blockDim.x + threadIdx.x) >> 5;
    int lane = threadIdx.x & 31;
    if (n >= N) return;
    float acc = 0.f;
    for (int j = lane; j < C; j += 32) acc += tmp[(size_t)n * C + j] * __ldg(&g2w[j]);
#pragma unroll
    for (int o = 16; o; o >>= 1) acc += __shfl_xor_sync(0xffffffffu, acc, o);
    if (lane == 0) {
        float ge = expf(acc + __ldg(&g2b[0]));
        gate[n] = ge;
        atomicAdd(&gd[batch[n]], ge);
    }
}

__global__ void k_pool(const int* __restrict__ batch, const float* __restrict__ gate,
                       const float* __restrict__ gd, const float* __restrict__ h2,
                       float* __restrict__ pool, int N, int C) {
    int n = (blockIdx.x * blockDim.x + threadIdx.x) >> 5;
    int lane = threadIdx.x & 31;
    if (n >= N) return;
    int b = batch[n];
    float w = gate[n] / gd[b];
    for (int c = lane; c < C; c += 32)
        atomicAdd(&pool[(size_t)b * C + c], w * h2[(size_t)n * C + c]);
}

__global__ void k_count(const int* __restrict__ dst, int* __restrict__ counts, int E) {
    for (int e = blockIdx.x * blockDim.x + threadIdx.x; e < E;
         e += gridDim.x * blockDim.x)
        atomicAdd(&counts[dst[e]], 1);
}

// ---------------- MLP head: one block per graph ----------------
__global__ void k_head(const float* __restrict__ pool, const float* __restrict__ gd,
                       const float* __restrict__ l1w, const float* __restrict__ l1b,
                       const float* __restrict__ l2w, const float* __restrict__ l2b,
                       float* __restrict__ out, int C) {
    __shared__ float sh[MAX_C];
    int g = blockIdx.x;
    int j = threadIdx.x;
    if (j < MAX_C) sh[j] = 0.f;
    __syncthreads();
    float inv = 1.f;
    if (gd) { float d = gd[g]; inv = (d > 0.f) ? 1.f / d : 0.f; }
    if (j < C) {
        float z = __ldg(&l1b[j]);
        for (int k = 0; k < C; k++)
            z += (pool[(size_t)g * C + k] * inv) * __ldg(&l1w[k * C + j]);
        z = fmaxf(z, 0.f);
        sh[j] = z * __ldg(&l2w[j]);
    }
    __syncthreads();
    if (j == 0) {
        float y = 0.f;
        for (int k = 0; k < C; k++) y += sh[k];
        out[g] = y + __ldg(&l2b[0]);
    }
}

// ---------------- launch ----------------
extern "C" void kernel_launch(void* const* d_in, const int* in_sizes, int n_in,
                              void* d_out, int out_size) {
    const float* x    = (const float*)d_in[0];
    const int*   ei   = (const int*)  d_in[1];   // [2, E]
    const int*   bat  = (const int*)  d_in[2];
    const float* Wl1  = (const float*)d_in[3];
    const float* Wr1  = (const float*)d_in[4];
    const float* att1 = (const float*)d_in[5];
    const float* b1   = (const float*)d_in[6];
    const float* Wl2  = (const float*)d_in[7];
    const float* Wr2  = (const float*)d_in[8];
    const float* att2 = (const float*)d_in[9];
    const float* b2   = (const float*)d_in[10];
    const float* g1w  = (const float*)d_in[11];
    const float* g1b  = (const float*)d_in[12];
    const float* g2w  = (const float*)d_in[13];
    const float* g2b  = (const float*)d_in[14];
    const float* l1w  = (const float*)d_in[15];
    const float* l1b  = (const float*)d_in[16];
    const float* l2w  = (const float*)d_in[17];
    const float* l2b  = (const float*)d_in[18];
    float* out = (float*)d_out;

    // Resolve TRUE device addresses of scratch symbols.
    float *xl1, *xr1, *O1, *h1, *ex1, *d1;
    float *xl2, *xr2, *O2, *h2, *ex2, *d2;
    float *tmp, *gate, *gd, *pool;
    int *counts, *rowptr, *cursor, *colsrc, *bsum, *gbarp;
    cudaGetSymbolAddress((void**)&xl1,  g_xl1);
    cudaGetSymbolAddress((void**)&xr1,  g_xr1);
    cudaGetSymbolAddress((void**)&O1,   g_O1);
    cudaGetSymbolAddress((void**)&h1,   g_h1);
    cudaGetSymbolAddress((void**)&ex1,  g_ex1);
    cudaGetSymbolAddress((void**)&d1,   g_d1);
    cudaGetSymbolAddress((void**)&xl2,  g_xl2);
    cudaGetSymbolAddress((void**)&xr2,  g_xr2);
    cudaGetSymbolAddress((void**)&O2,   g_O2);
    cudaGetSymbolAddress((void**)&h2,   g_h2);
    cudaGetSymbolAddress((void**)&ex2,  g_ex2);
    cudaGetSymbolAddress((void**)&d2,   g_d2);
    cudaGetSymbolAddress((void**)&tmp,  g_tmp);
    cudaGetSymbolAddress((void**)&gate, g_gate);
    cudaGetSymbolAddress((void**)&gd,   g_gd);
    cudaGetSymbolAddress((void**)&pool, g_pool);
    cudaGetSymbolAddress((void**)&counts, g_counts);
    cudaGetSymbolAddress((void**)&rowptr, g_rowptr);
    cudaGetSymbolAddress((void**)&cursor, g_cursor);
    cudaGetSymbolAddress((void**)&colsrc, g_colsrc);
    cudaGetSymbolAddress((void**)&bsum, g_bsum);
    cudaGetSymbolAddress((void**)&gbarp, g_gbar);

    // Derive ALL dimensions from runtime sizes.
    const int HC1 = in_sizes[6];            // |b1| = H*C
    const int C   = in_sizes[10];           // |b2| = C
    const int H   = HC1 / C;                // heads layer 1
    const int IN  = in_sizes[3] / HC1;      // |Wl1| = IN*HC1
    const int N   = in_sizes[0] / IN;       // |x| = N*IN
    const int E   = in_sizes[1] / 2;        // |edge_index| = 2*E
    const int G   = out_size;               // output graphs

    const int* src = ei;
    const int* dst = ei + E;

    const int TB = 256;
    auto cdiv = [](long long a, long long b) { return (int)((a + b - 1) / b); };

    const int node_warp_blocks = cdiv((long long)N * 32, TB);
    const bool fast = (C == 32) && (H == 2) && (HC1 == 64) && (IN == 128);

    if (fast) {
        // ---- reset grid-barrier words (capture-legal memset node) ----
        cudaMemsetAsync(gbarp, 0, 4 * sizeof(int), 0);

        // ---- MEGA CSR: init + count + scan in ONE persistent launch ----
        k_csr_mega<<<256, 256>>>(dst, counts, rowptr, cursor, bsum,
                                 gd, pool, gbarp, N, E, G, C);

        // ---- GEMM1 overlapped with ILP-8 CSR fill (block-role fusion) ----
        int gemmBlocks = cdiv(N, 32);
        int fillBlocks = cdiv(max(E >> 3, 1), TB);
        k_gemm1_fill<128><<<gemmBlocks + fillBlocks, TB>>>(
            x, Wl1, Wr1, xl1, xr1, N, gemmBlocks, src, dst, cursor, colsrc, E);

        // ---- layer 1 attention (unroll-2) ----
        k_gat_fused2_h2<<<node_warp_blocks, TB>>>(rowptr, colsrc, xl1, xr1, att1, b1, h1, N);

        // ---- layer 2 GEMM (prepacked {L,R}, NPW=8) ----
        k_gemm_dual32<64><<<cdiv(N, 64), TB>>>(h1, Wl2, Wr2, xl2, xr2, N);

        // ---- layer 2 attention + gate + pool, fully fused (unroll-2) ----
        k_gat2_gate_pool<<<node_warp_blocks, TB>>>(rowptr, colsrc, xl2, xr2, att2, b2,
                                                   g1w, g1b, g2w, g2b, bat, gd, pool, N);

        k_head<<<G, 64>>>(pool, gd, l1w, l1b, l2w, l2b, out, C);
    } else {
        // ---- generic fallback (proven R5 path) ----
        k_init<<<cdiv((long long)N * HC1, TB), TB>>>(counts, gd, pool, O1, O2, d1, d2,
                                                     N, G, HC1, C, H);
        const int edge_warp_blocks = cdiv((long long)E * 32, TB);
        k_gemm<<<cdiv((long long)N * HC1, TB), TB>>>(x, Wl1, nullptr, xl1, N, IN, HC1, 0);
        k_gemm<<<cdiv((long long)N * HC1, TB), TB>>>(x, Wr1, nullptr, xr1, N, IN, HC1, 0);
        k_score<<<edge_warp_blocks, TB>>>(src, dst, xl1, xr1, att1, ex1, d1, E, H, C, HC1);
        k_agg<<<edge_warp_blocks, TB>>>(src, dst, xl1, ex1, d1, O1, E, H, C, HC1);
        k_relu_bias<<<cdiv((long long)N * HC1, TB), TB>>>(O1, b1, h1, N * HC1, HC1);

        k_gemm<<<cdiv((long long)N * C, TB), TB>>>(h1, Wl2, nullptr, xl2, N, HC1, C, 0);
        k_gemm<<<cdiv((long long)N * C, TB), TB>>>(h1, Wr2, nullptr, xr2, N, HC1, C, 0);
        k_score<<<edge_warp_blocks, TB>>>(src, dst, xl2, xr2, att2, ex2, d2, E, 1, C, C);
        k_agg<<<edge_warp_blocks, TB>>>(src, dst, xl2, ex2, d2, O2, E, 1, C, C);
        k_relu_bias<<<cdiv((long long)N * C, TB), TB>>>(O2, b2, h2, N * C, C);

        k_gemm<<<cdiv((long long)N * C, TB), TB>>>(h2, g1w, g1b, tmp, N, C, C, 1);
        k_gate2<<<node_warp_blocks, TB>>>(tmp, g2w, g2b, bat, gate, gd, N, C);
        k_pool<<<node_warp_blocks, TB>>>(bat, gate, gd, h2, pool, N, C);

        k_head<<<G, 64>>>(pool, nullptr, l1w, l1b, l2w, l2b, out, C);
    }
}

// round 16
// speedup vs baseline: 1.0043x; 1.0043x over previous
#include <cuda_runtime.h>
#include <math.h>

// Capacity bounds for static scratch (actual dims derived at runtime).
#define MAX_N  150000
#define MAX_E  2400000
#define MAX_HC 96
#define MAX_C  48
#define MAX_H  4
#define MAX_G  512

#define CAP_NHC ((long long)MAX_N * MAX_HC)
#define CAP_NC  ((long long)MAX_N * MAX_C)
#define CAP_EH  ((long long)MAX_E * MAX_H)
#define CAP_E   ((long long)MAX_E)
#define CAP_NH  ((long long)MAX_N * MAX_H)
#define CAP_N   ((long long)MAX_N)
#define CAP_GC  ((long long)MAX_G * MAX_C)
#define CAP_G   ((long long)MAX_G)

// ---------------- static scratch (no allocation allowed) ----------------
// Only ever accessed through pointers from cudaGetSymbolAddress (GB300 ATS
// silently dereferences the host shadow if you pass the symbol as an arg!).
__device__ float g_xl1[CAP_NHC];
__device__ float g_xr1[CAP_NHC];
__device__ float g_O1 [CAP_NHC];     // fallback path only
__device__ float g_h1 [CAP_NHC];
__device__ float g_ex1[CAP_EH];      // fallback path only
__device__ float g_d1 [CAP_NH];      // fallback path only

__device__ float g_xl2[CAP_NC];
__device__ float g_xr2[CAP_NC];
__device__ float g_O2 [CAP_NC];      // fallback path only
__device__ float g_h2 [CAP_NC];      // fallback path only
__device__ float g_ex2[CAP_E];       // fallback path only
__device__ float g_d2 [CAP_N];       // fallback path only

__device__ float g_tmp [CAP_NC];
__device__ float g_gate[CAP_N];
__device__ float g_gd  [CAP_G];
__device__ float g_pool[CAP_GC];

// CSR scratch
__device__ int g_counts[CAP_N];
__device__ int g_rowptr[CAP_N + 1];
__device__ int g_cursor[CAP_N];
__device__ int g_colsrc[CAP_E];
__device__ int g_bsum[256];
__device__ int g_gbar[4];            // software grid-barrier counters

__device__ __forceinline__ float lrelu(float v) { return v > 0.f ? v : 0.2f * v; }

// ---- packed f32x2 helpers (Blackwell FFMA2; ptxas won't emit from C++) ----
__device__ __forceinline__ unsigned long long pack2(float x, float y) {
    unsigned long long r;
    asm("mov.b64 %0, {%1, %2};" : "=l"(r) : "f"(x), "f"(y));
    return r;
}
__device__ __forceinline__ void fma2(unsigned long long& d,
                                     unsigned long long a, unsigned long long b) {
    asm("fma.rn.f32x2 %0, %1, %2, %0;" : "+l"(d) : "l"(a), "l"(b));
}
__device__ __forceinline__ float2 unpack2(unsigned long long v) {
    float2 r;
    asm("mov.b64 {%0, %1}, %2;" : "=f"(r.x), "=f"(r.y) : "l"(v));
    return r;
}

// ---- software grid barrier (all blocks co-resident by construction) ----
__device__ __forceinline__ void gbar(int* bar, int expected) {
    __syncthreads();
    if (threadIdx.x == 0) {
        __threadfence();
        atomicAdd(bar, 1);
        while (*(volatile int*)bar < expected) { }
        __threadfence();
    }
    __syncthreads();
}

// ---------------- init (fallback path only) ----------------
__global__ void k_init(int* counts, float* gd, float* pool,
                       float* O1, float* O2, float* d1, float* d2,
                       int N, int G, int HC1, int C, int H) {
    long long tot = (long long)N * HC1;
    long long stride = (long long)gridDim.x * blockDim.x;
    for (long long i = (long long)blockIdx.x * blockDim.x + threadIdx.x;
         i < tot; i += stride) {
        O1[i] = 0.f;
        if (i < (long long)N * C) O2[i] = 0.f;
        if (i < (long long)N * H) d1[i] = 0.f;
        if (i < N)                { d2[i] = 0.f; counts[i] = 0; }
        if (i < (long long)G * C) pool[i] = 0.f;
        if (i < G)                gd[i] = 0.f;
    }
}

// ---------------- MEGA CSR: init + count + scan, one launch ----------------
__global__ void k_csr_mega(const int* __restrict__ dst,
                           int* __restrict__ counts, int* __restrict__ rowptr,
                           int* __restrict__ cursor, int* __restrict__ bsum,
                           float* __restrict__ gd, float* __restrict__ pool,
                           int* __restrict__ bar,
                           int Nn, int E, int G, int C) {
    const int nb = gridDim.x;                 // 256
    const int t = threadIdx.x;
    const int bid = blockIdx.x;
    const int gtid = bid * 256 + t;
    const int gstride = nb * 256;

    // ---- phase 0: zero counts + gd + pool ----
    for (int i = gtid; i < Nn; i += gstride) counts[i] = 0;
    if (bid == 0) {
        for (int i = t; i < G * C; i += 256) pool[i] = 0.f;
        for (int i = t; i < G; i += 256) gd[i] = 0.f;
    }
    gbar(&bar[0], nb);

    // ---- phase 1: histogram (ILP-4 int4 when aligned) ----
    if ((E & 3) == 0) {
        int E4 = E >> 2;
        for (int i = gtid; i < E4; i += gstride) {
            int4 v = __ldg(&((const int4*)dst)[i]);
            atomicAdd(&counts[v.x], 1);
            atomicAdd(&counts[v.y], 1);
            atomicAdd(&counts[v.z], 1);
            atomicAdd(&counts[v.w], 1);
        }
    } else {
        for (int e = gtid; e < E; e += gstride)
            atomicAdd(&counts[dst[e]], 1);
    }
    gbar(&bar[1], nb);

    // ---- phase 2: per-block sums over contiguous chunk ----
    __shared__ int sh[256];
    __shared__ int sb[256];
    const int chunk = (Nn + nb - 1) / nb;
    {
        int beg = bid * chunk;
        int end = min(beg + chunk, Nn);
        int s = 0;
        for (int i = beg + t; i < end; i += 256) s += counts[i];
        sh[t] = s;
        __syncthreads();
        for (int d = 128; d; d >>= 1) {
            if (t < d) sh[t] += sh[t + d];
            __syncthreads();
        }
        if (t == 0) bsum[bid] = sh[0];
    }
    gbar(&bar[2], nb);

    // ---- phase 3: cross-block scan + local exclusive scan + write ----
    sb[t] = bsum[t];
    __syncthreads();
    for (int d = 1; d < 256; d <<= 1) {
        int v = (t >= d) ? sb[t - d] : 0;
        __syncthreads();
        sb[t] += v;
        __syncthreads();
    }
    int blockoff = (bid == 0) ? 0 : sb[bid - 1];

    int bbeg = bid * chunk;
    int bend = min(bbeg + chunk, Nn);
    int tchunk = (chunk + 255) / 256;
    int tb = bbeg + t * tchunk;
    int te = min(tb + tchunk, bend);
    int s = 0;
    for (int i = tb; i < te; i++) s += counts[i];
    int orig = s;
    sh[t] = s;
    __syncthreads();
    for (int d = 1; d < 256; d <<= 1) {
        int v = (t >= d) ? sh[t - d] : 0;
        __syncthreads();
        sh[t] += v;
        __syncthreads();
    }
    int off = blockoff + sh[t] - orig;
    for (int i = tb; i < te; i++) {
        rowptr[i] = off;
        cursor[i] = off;
        off += counts[i];
    }
    if (bid == nb - 1 && t == 255) rowptr[Nn] = E;
}

// ---------------- FUSED: GEMM1 (FFMA2, prepacked W) + ILP-8 CSR fill -------
template <int K>
__global__ void k_gemm1_fill(const float* __restrict__ X,
                             const float* __restrict__ Wl, const float* __restrict__ Wr,
                             float* __restrict__ Yl, float* __restrict__ Yr, int n,
                             int gemmBlocks,
                             const int* __restrict__ src, const int* __restrict__ dst,
                             int* __restrict__ cursor, int* __restrict__ colsrc, int E) {
    constexpr int J = 64;
    constexpr int NPW = 4;
    constexpr int XR = K / 32;
    __shared__ float2 WsLP[K * 32];   // packed (W[k][c], W[k][c+32])
    __shared__ float2 WsRP[K * 32];

    int tid = threadIdx.x;

    if (blockIdx.x >= gemmBlocks) {
        // ---- fill role (ILP-8) ----
        int i = (blockIdx.x - gemmBlocks) * blockDim.x + tid;
        int E8 = E >> 3;
        if (i < E8) {
            int4 da = __ldg(&((const int4*)dst)[2 * i]);
            int4 db = __ldg(&((const int4*)dst)[2 * i + 1]);
            int4 sa = __ldg(&((const int4*)src)[2 * i]);
            int4 sb = __ldg(&((const int4*)src)[2 * i + 1]);
            int p0 = atomicAdd(&cursor[da.x], 1);
            int p1 = atomicAdd(&cursor[da.y], 1);
            int p2 = atomicAdd(&cursor[da.z], 1);
            int p3 = atomicAdd(&cursor[da.w], 1);
            int p4 = atomicAdd(&cursor[db.x], 1);
            int p5 = atomicAdd(&cursor[db.y], 1);
            int p6 = atomicAdd(&cursor[db.z], 1);
            int p7 = atomicAdd(&cursor[db.w], 1);
            colsrc[p0] = sa.x; colsrc[p1] = sa.y; colsrc[p2] = sa.z; colsrc[p3] = sa.w;
            colsrc[p4] = sb.x; colsrc[p5] = sb.y; colsrc[p6] = sb.z; colsrc[p7] = sb.w;
        }
        if (i < (E & 7)) {
            int e = (E8 << 3) + i;
            int pos = atomicAdd(&cursor[dst[e]], 1);
            colsrc[pos] = src[e];
        }
        return;
    }

    // ---- GEMM role (R10-proven: x in registers, shfl broadcast) ----
    for (int l = tid; l < K * 32; l += 256) {
        int k = l >> 5, c = l & 31;
        WsLP[l] = make_float2(Wl[k * J + c], Wl[k * J + 32 + c]);
        WsRP[l] = make_float2(Wr[k * J + c], Wr[k * J + 32 + c]);
    }
    __syncthreads();

    int warp = tid >> 5, lane = tid & 31;
    int base = (blockIdx.x * 8 + warp) * NPW;
    if (base >= n) return;

    float xreg[NPW][XR];
#pragma unroll
    for (int p = 0; p < NPW; p++) {
        int node = base + p;
        bool ok = node < n;
#pragma unroll
        for (int i = 0; i < XR; i++)
            xreg[p][i] = ok ? X[(size_t)node * K + i * 32 + lane] : 0.f;
    }

    unsigned long long aL[NPW], aR[NPW];
#pragma unroll
    for (int p = 0; p < NPW; p++) { aL[p] = pack2(0.f, 0.f); aR[p] = pack2(0.f, 0.f); }

    const unsigned long long* WL = (const unsigned long long*)WsLP;
    const unsigned long long* WR = (const unsigned long long*)WsRP;
#pragma unroll
    for (int ko = 0; ko < XR; ko++) {
#pragma unroll
        for (int ki = 0; ki < 32; ki++) {
            int k = ko * 32 + ki;
            unsigned long long wlp = WL[k * 32 + lane];
            unsigned long long wrp = WR[k * 32 + lane];
#pragma unroll
            for (int p = 0; p < NPW; p++) {
                float xk = __shfl_sync(0xffffffffu, xreg[p][ko], ki);
                unsigned long long xkp = pack2(xk, xk);
                fma2(aL[p], xkp, wlp);
                fma2(aR[p], xkp, wrp);
            }
        }
    }
#pragma unroll
    for (int p = 0; p < NPW; p++) {
        int node = base + p;
        if (node < n) {
            float2 l2 = unpack2(aL[p]), r2 = unpack2(aR[p]);
            Yl[(size_t)node * J + lane]      = l2.x;
            Yl[(size_t)node * J + 32 + lane] = l2.y;
            Yr[(size_t)node * J + lane]      = r2.x;
            Yr[(size_t)node * J + 32 + lane] = r2.y;
        }
    }
}

// ---------------- DUAL GEMM layer 2: FFMA2 {L,R}-prepacked, J=32, NPW=6 ----
// R14 (NPW=4): occ 66%, L1 80% — crossbar-bound. R15 (NPW=8): occ 34%, L1 69%
// — latency-exposed. NPW=6 sits between: ~56 regs -> ~50% occ with 6-way LDS
// amortization.
template <int K>
__global__ void __launch_bounds__(256)
k_gemm_dual32(const float* __restrict__ X,
              const float* __restrict__ Wl, const float* __restrict__ Wr,
              float* __restrict__ Yl, float* __restrict__ Yr, int n) {
    constexpr int J = 32;
    constexpr int NPW = 6;
    constexpr int XR = K / 32;
    __shared__ float2 WsP[K * 32];    // packed (Wl[k][c], Wr[k][c])
    int tid = threadIdx.x;
    for (int l = tid; l < K * 32; l += 256) {
        int k = l >> 5, c = l & 31;
        WsP[l] = make_float2(Wl[k * J + c], Wr[k * J + c]);
    }
    __syncthreads();

    int warp = tid >> 5, lane = tid & 31;
    int base = (blockIdx.x * 8 + warp) * NPW;
    if (base >= n) return;

    float xreg[NPW][XR];
#pragma unroll
    for (int p = 0; p < NPW; p++) {
        int node = base + p;
        bool ok = node < n;
#pragma unroll
        for (int i = 0; i < XR; i++)
            xreg[p][i] = ok ? X[(size_t)node * K + i * 32 + lane] : 0.f;
    }

    unsigned long long a[NPW];   // packed {accL, accR}
#pragma unroll
    for (int p = 0; p < NPW; p++) a[p] = pack2(0.f, 0.f);

    const unsigned long long* WP = (const unsigned long long*)WsP;
#pragma unroll
    for (int ko = 0; ko < XR; ko++) {
#pragma unroll
        for (int ki = 0; ki < 32; ki++) {
            int k = ko * 32 + ki;
            unsigned long long wp = WP[k * 32 + lane];
#pragma unroll
            for (int p = 0; p < NPW; p++) {
                float xk = __shfl_sync(0xffffffffu, xreg[p][ko], ki);
                fma2(a[p], pack2(xk, xk), wp);
            }
        }
    }
#pragma unroll
    for (int p = 0; p < NPW; p++) {
        int node = base + p;
        if (node < n) {
            float2 lr = unpack2(a[p]);
            Yl[(size_t)node * J + lane] = lr.x;
            Yr[(size_t)node * J + lane] = lr.y;
        }
    }
}

// ---------------- generic GEMM (fallback): Y = X@W (+bias, relu) -----------
__global__ void k_gemm(const float* __restrict__ X, const float* __restrict__ W,
                       const float* __restrict__ bias, float* __restrict__ Y,
                       int n, int K, int J, int do_relu) {
    int total = n * J;
    for (int idx = blockIdx.x * blockDim.x + threadIdx.x; idx < total;
         idx += gridDim.x * blockDim.x) {
        int r = idx / J;
        int j = idx - r * J;
        const float* xrow = X + (size_t)r * K;
        float acc = 0.f;
        int k = 0;
        for (; k + 4 <= K; k += 4) {
            acc += xrow[k]     * __ldg(&W[(k)     * J + j]);
            acc += xrow[k + 1] * __ldg(&W[(k + 1) * J + j]);
            acc += xrow[k + 2] * __ldg(&W[(k + 2) * J + j]);
            acc += xrow[k + 3] * __ldg(&W[(k + 3) * J + j]);
        }
        for (; k < K; k++) acc += xrow[k] * __ldg(&W[k * J + j]);
        if (bias) acc += __ldg(&bias[j]);
        if (do_relu) acc = fmaxf(acc, 0.f);
        Y[idx] = acc;
    }
}

// ---------------- FAST PATH layer 1: fused GATv2, float2, H=2, unroll-2 ----
__global__ void k_gat_fused2_h2(const int* __restrict__ rowptr, const int* __restrict__ colsrc,
                                const float* __restrict__ xl, const float* __restrict__ xr,
                                const float* __restrict__ att, const float* __restrict__ bias,
                                float* __restrict__ hout, int Nn) {
    int n = (blockIdx.x * blockDim.x + threadIdx.x) >> 5;
    int lane = threadIdx.x & 31;
    if (n >= Nn) return;

    const float2* xl2 = (const float2*)xl;
    float2 xrr = ((const float2*)xr)[(size_t)n * 32 + lane];
    float2 av  = __ldg(&((const float2*)att)[lane]);
    float accx = 0.f, accy = 0.f, den = 0.f;

    int beg = rowptr[n], end = rowptr[n + 1];
    int i = beg;
    for (; i + 1 < end; i += 2) {
        int s0 = __ldg(&colsrc[i]);
        int s1 = __ldg(&colsrc[i + 1]);
        float2 v0 = __ldg(&xl2[(size_t)s0 * 32 + lane]);
        float2 v1 = __ldg(&xl2[(size_t)s1 * 32 + lane]);
        float sc0 = lrelu(v0.x + xrr.x) * av.x + lrelu(v0.y + xrr.y) * av.y;
        float sc1 = lrelu(v1.x + xrr.x) * av.x + lrelu(v1.y + xrr.y) * av.y;
        sc0 += __shfl_xor_sync(0xffffffffu, sc0, 8);
        sc1 += __shfl_xor_sync(0xffffffffu, sc1, 8);
        sc0 += __shfl_xor_sync(0xffffffffu, sc0, 4);
        sc1 += __shfl_xor_sync(0xffffffffu, sc1, 4);
        sc0 += __shfl_xor_sync(0xffffffffu, sc0, 2);
        sc1 += __shfl_xor_sync(0xffffffffu, sc1, 2);
        sc0 += __shfl_xor_sync(0xffffffffu, sc0, 1);
        sc1 += __shfl_xor_sync(0xffffffffu, sc1, 1);
        float a0 = __expf(sc0), a1 = __expf(sc1);
        den += a0 + a1;
        accx = fmaf(a0, v0.x, accx); accx = fmaf(a1, v1.x, accx);
        accy = fmaf(a0, v0.y, accy); accy = fmaf(a1, v1.y, accy);
    }
    if (i < end) {
        int s = __ldg(&colsrc[i]);
        float2 v = __ldg(&xl2[(size_t)s * 32 + lane]);
        float sc = lrelu(v.x + xrr.x) * av.x + lrelu(v.y + xrr.y) * av.y;
        sc += __shfl_xor_sync(0xffffffffu, sc, 8);
        sc += __shfl_xor_sync(0xffffffffu, sc, 4);
        sc += __shfl_xor_sync(0xffffffffu, sc, 2);
        sc += __shfl_xor_sync(0xffffffffu, sc, 1);
        float a = __expf(sc);
        den += a;
        accx = fmaf(a, v.x, accx);
        accy = fmaf(a, v.y, accy);
    }
    float2 bv = __ldg(&((const float2*)bias)[lane]);
    float inv = (den > 0.f) ? 1.f / den : 0.f;
    float2 o;
    o.x = fmaxf(accx * inv + bv.x, 0.f);
    o.y = fmaxf(accy * inv + bv.y, 0.f);
    ((float2*)hout)[(size_t)n * 32 + lane] = o;
}

// ---------------- FAST PATH layer 2 + gate + pool, all fused, unroll-2 -----
__global__ void k_gat2_gate_pool(const int* __restrict__ rowptr, const int* __restrict__ colsrc,
                                 const float* __restrict__ xl, const float* __restrict__ xr,
                                 const float* __restrict__ att, const float* __restrict__ bias,
                                 const float* __restrict__ g1w, const float* __restrict__ g1b,
                                 const float* __restrict__ g2w, const float* __restrict__ g2b,
                                 const int* __restrict__ batch,
                                 float* __restrict__ gd, float* __restrict__ pool, int Nn) {
    int n = (blockIdx.x * blockDim.x + threadIdx.x) >> 5;
    int lane = threadIdx.x & 31;
    if (n >= Nn) return;
    int hw = lane >> 4;
    int l16 = lane & 15;
    unsigned hmask = hw ? 0xffff0000u : 0x0000ffffu;

    const float2* xl2 = (const float2*)xl;
    float2 xrr = ((const float2*)xr)[(size_t)n * 16 + l16];
    float2 av  = __ldg(&((const float2*)att)[l16]);
    float accx = 0.f, accy = 0.f, den = 0.f;

    int beg = rowptr[n], end = rowptr[n + 1];
    int i = beg + hw;
    for (; i + 2 < end; i += 4) {
        int s0 = __ldg(&colsrc[i]);
        int s1 = __ldg(&colsrc[i + 2]);
        float2 v0 = __ldg(&xl2[(size_t)s0 * 16 + l16]);
        float2 v1 = __ldg(&xl2[(size_t)s1 * 16 + l16]);
        float sc0 = lrelu(v0.x + xrr.x) * av.x + lrelu(v0.y + xrr.y) * av.y;
        float sc1 = lrelu(v1.x + xrr.x) * av.x + lrelu(v1.y + xrr.y) * av.y;
        sc0 += __shfl_xor_sync(hmask, sc0, 8);
        sc1 += __shfl_xor_sync(hmask, sc1, 8);
        sc0 += __shfl_xor_sync(hmask, sc0, 4);
        sc1 += __shfl_xor_sync(hmask, sc1, 4);
        sc0 += __shfl_xor_sync(hmask, sc0, 2);
        sc1 += __shfl_xor_sync(hmask, sc1, 2);
        sc0 += __shfl_xor_sync(hmask, sc0, 1);
        sc1 += __shfl_xor_sync(hmask, sc1, 1);
        float a0 = __expf(sc0), a1 = __expf(sc1);
        den += a0 + a1;
        accx = fmaf(a0, v0.x, accx); accx = fmaf(a1, v1.x, accx);
        accy = fmaf(a0, v0.y, accy); accy = fmaf(a1, v1.y, accy);
    }
    if (i < end) {
        int s = __ldg(&colsrc[i]);
        float2 v = __ldg(&xl2[(size_t)s * 16 + l16]);
        float sc = lrelu(v.x + xrr.x) * av.x + lrelu(v.y + xrr.y) * av.y;
        sc += __shfl_xor_sync(hmask, sc, 8);
        sc += __shfl_xor_sync(hmask, sc, 4);
        sc += __shfl_xor_sync(hmask, sc, 2);
        sc += __shfl_xor_sync(hmask, sc, 1);
        float a = __expf(sc);
        den += a;
        accx = fmaf(a, v.x, accx);
        accy = fmaf(a, v.y, accy);
    }
    den  += __shfl_xor_sync(0xffffffffu, den, 16);
    accx += __shfl_xor_sync(0xffffffffu, accx, 16);
    accy += __shfl_xor_sync(0xffffffffu, accy, 16);
    float2 bv = __ldg(&((const float2*)bias)[l16]);
    float inv = (den > 0.f) ? 1.f / den : 0.f;
    float2 o;
    o.x = fmaxf(accx * inv + bv.x, 0.f);
    o.y = fmaxf(accy * inv + bv.y, 0.f);

    // gate MLP: lane j computes t[j] = relu(sum_k h[k]*g1w[k][j] + g1b[j])
    float t = __ldg(&g1b[lane]);
    const float* g1wj = g1w + lane;
#pragma unroll
    for (int k = 0; k < 32; k += 2) {
        float hx = __shfl_sync(0xffffffffu, o.x, k >> 1);
        float hy = __shfl_sync(0xffffffffu, o.y, k >> 1);
        t = fmaf(hx, __ldg(&g1wj[k * 32]), t);
        t = fmaf(hy, __ldg(&g1wj[(k + 1) * 32]), t);
    }
    t = fmaxf(t, 0.f);
    float y = t * __ldg(&g2w[lane]);
#pragma unroll
    for (int of = 16; of; of >>= 1) y += __shfl_xor_sync(0xffffffffu, y, of);
    float ge = __expf(y + __ldg(&g2b[0]));

    float ax = __shfl_sync(0xffffffffu, o.x, lane >> 1);
    float ay = __shfl_sync(0xffffffffu, o.y, lane >> 1);
    float hj = (lane & 1) ? ay : ax;
    int b = batch[n];
    atomicAdd(&pool[(size_t)b * 32 + lane], ge * hj);
    if (lane == 0) atomicAdd(&gd[b], ge);
}

// ---------------- FALLBACK: edge kernels (any shape) ----------------
__global__ void k_score(const int* __restrict__ src, const int* __restrict__ dst,
                        const float* __restrict__ xl, const float* __restrict__ xr,
                        const float* __restrict__ att, float* __restrict__ ex,
                        float* __restrict__ den, int E, int H, int C, int HC) {
    int e = (blockIdx.x * blockDim.x + threadIdx.x) >> 5;
    int lane = threadIdx.x & 31;
    if (e >= E) return;
    int s = src[e], d = dst[e];
    for (int h = 0; h < H; h++) {
        float acc = 0.f;
        for (int c = lane; c < C; c += 32) {
            float v = xl[(size_t)s * HC + h * C + c] + xr[(size_t)d * HC + h * C + c];
            acc += lrelu(v) * __ldg(&att[h * C + c]);
        }
#pragma unroll
        for (int o = 16; o; o >>= 1) acc += __shfl_xor_sync(0xffffffffu, acc, o);
        if (lane == 0) {
            float t = expf(acc);
            ex[(size_t)e * H + h] = t;
            atomicAdd(&den[d * H + h], t);
        }
    }
}

__global__ void k_agg(const int* __restrict__ src, const int* __restrict__ dst,
                      const float* __restrict__ xl, const float* __restrict__ ex,
                      const float* __restrict__ den, float* __restrict__ O,
                      int E, int H, int C, int HC) {
    int e = (blockIdx.x * blockDim.x + threadIdx.x) >> 5;
    int lane = threadIdx.x & 31;
    if (e >= E) return;
    int s = src[e], d = dst[e];
    for (int h = 0; h < H; h++) {
        float alpha = ex[(size_t)e * H + h] / den[d * H + h];
        for (int c = lane; c < C; c += 32)
            atomicAdd(&O[(size_t)d * HC + h * C + c],
                      alpha * xl[(size_t)s * HC + h * C + c]);
    }
}

__global__ void k_relu_bias(const float* __restrict__ O, const float* __restrict__ b,
                            float* __restrict__ hout, int total, int HC) {
    for (int i = blockIdx.x * blockDim.x + threadIdx.x; i < total;
         i += gridDim.x * blockDim.x) {
        int col = i % HC;
        hout[i] = fmaxf(O[i] + __ldg(&b[col]), 0.f);
    }
}

__global__ void k_gate2(const float* __restrict__ tmp, const float* __restrict__ g2w,
                        const float* __restrict__ g2b, const int* __restrict__ batch,
                        float* __restrict__ gate, float* __restrict__ gd, int N, int C) {
    int n = (blockIdx.x * blockDim.x + threadIdx.x) >> 5;
    int lane = threadIdx.x & 31;
    if (n >= N) return;
    float acc = 0.f;
    for (int j = lane; j < C; j += 32) acc += tmp[(size_t)n * C + j] * __ldg(&g2w[j]);
#pragma unroll
    for (int o = 16; o; o >>= 1) acc += __shfl_xor_sync(0xffffffffu, acc, o);
    if (lane == 0) {
        float ge = expf(acc + __ldg(&g2b[0]));
        gate[n] = ge;
        atomicAdd(&gd[batch[n]], ge);
    }
}

__global__ void k_pool(const int* __restrict__ batch, const float* __restrict__ gate,
                       const float* __restrict__ gd, const float* __restrict__ h2,
                       float* __restrict__ pool, int N, int C) {
    int n = (blockIdx.x * blockDim.x + threadIdx.x) >> 5;
    int lane = threadIdx.x & 31;
    if (n >= N) return;
    int b = batch[n];
    float w = gate[n] / gd[b];
    for (int c = lane; c < C; c += 32)
        atomicAdd(&pool[(size_t)b * C + c], w * h2[(size_t)n * C + c]);
}

__global__ void k_count(const int* __restrict__ dst, int* __restrict__ counts, int E) {
    for (int e = blockIdx.x * blockDim.x + threadIdx.x; e < E;
         e += gridDim.x * blockDim.x)
        atomicAdd(&counts[dst[e]], 1);
}

// ---------------- MLP head: one block per graph ----------------
__global__ void k_head(const float* __restrict__ pool, const float* __restrict__ gd,
                       const float* __restrict__ l1w, const float* __restrict__ l1b,
                       const float* __restrict__ l2w, const float* __restrict__ l2b,
                       float* __restrict__ out, int C) {
    __shared__ float sh[MAX_C];
    int g = blockIdx.x;
    int j = threadIdx.x;
    if (j < MAX_C) sh[j] = 0.f;
    __syncthreads();
    float inv = 1.f;
    if (gd) { float d = gd[g]; inv = (d > 0.f) ? 1.f / d : 0.f; }
    if (j < C) {
        float z = __ldg(&l1b[j]);
        for (int k = 0; k < C; k++)
            z += (pool[(size_t)g * C + k] * inv) * __ldg(&l1w[k * C + j]);
        z = fmaxf(z, 0.f);
        sh[j] = z * __ldg(&l2w[j]);
    }
    __syncthreads();
    if (j == 0) {
        float y = 0.f;
        for (int k = 0; k < C; k++) y += sh[k];
        out[g] = y + __ldg(&l2b[0]);
    }
}

// ---------------- launch ----------------
extern "C" void kernel_launch(void* const* d_in, const int* in_sizes, int n_in,
                              void* d_out, int out_size) {
    const float* x    = (const float*)d_in[0];
    const int*   ei   = (const int*)  d_in[1];   // [2, E]
    const int*   bat  = (const int*)  d_in[2];
    const float* Wl1  = (const float*)d_in[3];
    const float* Wr1  = (const float*)d_in[4];
    const float* att1 = (const float*)d_in[5];
    const float* b1   = (const float*)d_in[6];
    const float* Wl2  = (const float*)d_in[7];
    const float* Wr2  = (const float*)d_in[8];
    const float* att2 = (const float*)d_in[9];
    const float* b2   = (const float*)d_in[10];
    const float* g1w  = (const float*)d_in[11];
    const float* g1b  = (const float*)d_in[12];
    const float* g2w  = (const float*)d_in[13];
    const float* g2b  = (const float*)d_in[14];
    const float* l1w  = (const float*)d_in[15];
    const float* l1b  = (const float*)d_in[16];
    const float* l2w  = (const float*)d_in[17];
    const float* l2b  = (const float*)d_in[18];
    float* out = (float*)d_out;

    // Resolve TRUE device addresses of scratch symbols.
    float *xl1, *xr1, *O1, *h1, *ex1, *d1;
    float *xl2, *xr2, *O2, *h2, *ex2, *d2;
    float *tmp, *gate, *gd, *pool;
    int *counts, *rowptr, *cursor, *colsrc, *bsum, *gbarp;
    cudaGetSymbolAddress((void**)&xl1,  g_xl1);
    cudaGetSymbolAddress((void**)&xr1,  g_xr1);
    cudaGetSymbolAddress((void**)&O1,   g_O1);
    cudaGetSymbolAddress((void**)&h1,   g_h1);
    cudaGetSymbolAddress((void**)&ex1,  g_ex1);
    cudaGetSymbolAddress((void**)&d1,   g_d1);
    cudaGetSymbolAddress((void**)&xl2,  g_xl2);
    cudaGetSymbolAddress((void**)&xr2,  g_xr2);
    cudaGetSymbolAddress((void**)&O2,   g_O2);
    cudaGetSymbolAddress((void**)&h2,   g_h2);
    cudaGetSymbolAddress((void**)&ex2,  g_ex2);
    cudaGetSymbolAddress((void**)&d2,   g_d2);
    cudaGetSymbolAddress((void**)&tmp,  g_tmp);
    cudaGetSymbolAddress((void**)&gate, g_gate);
    cudaGetSymbolAddress((void**)&gd,   g_gd);
    cudaGetSymbolAddress((void**)&pool, g_pool);
    cudaGetSymbolAddress((void**)&counts, g_counts);
    cudaGetSymbolAddress((void**)&rowptr, g_rowptr);
    cudaGetSymbolAddress((void**)&cursor, g_cursor);
    cudaGetSymbolAddress((void**)&colsrc, g_colsrc);
    cudaGetSymbolAddress((void**)&bsum, g_bsum);
    cudaGetSymbolAddress((void**)&gbarp, g_gbar);

    // Derive ALL dimensions from runtime sizes.
    const int HC1 = in_sizes[6];            // |b1| = H*C
    const int C   = in_sizes[10];           // |b2| = C
    const int H   = HC1 / C;                // heads layer 1
    const int IN  = in_sizes[3] / HC1;      // |Wl1| = IN*HC1
    const int N   = in_sizes[0] / IN;       // |x| = N*IN
    const int E   = in_sizes[1] / 2;        // |edge_index| = 2*E
    const int G   = out_size;               // output graphs

    const int* src = ei;
    const int* dst = ei + E;

    const int TB = 256;
    auto cdiv = [](long long a, long long b) { return (int)((a + b - 1) / b); };

    const int node_warp_blocks = cdiv((long long)N * 32, TB);
    const bool fast = (C == 32) && (H == 2) && (HC1 == 64) && (IN == 128);

    if (fast) {
        // ---- reset grid-barrier words (capture-legal memset node) ----
        cudaMemsetAsync(gbarp, 0, 4 * sizeof(int), 0);

        // ---- MEGA CSR: init + count + scan in ONE persistent launch ----
        k_csr_mega<<<256, 256>>>(dst, counts, rowptr, cursor, bsum,
                                 gd, pool, gbarp, N, E, G, C);

        // ---- GEMM1 overlapped with ILP-8 CSR fill (block-role fusion) ----
        int gemmBlocks = cdiv(N, 32);
        int fillBlocks = cdiv(max(E >> 3, 1), TB);
        k_gemm1_fill<128><<<gemmBlocks + fillBlocks, TB>>>(
            x, Wl1, Wr1, xl1, xr1, N, gemmBlocks, src, dst, cursor, colsrc, E);

        // ---- layer 1 attention (unroll-2) ----
        k_gat_fused2_h2<<<node_warp_blocks, TB>>>(rowptr, colsrc, xl1, xr1, att1, b1, h1, N);

        // ---- layer 2 GEMM (prepacked {L,R}, NPW=6) ----
        k_gemm_dual32<64><<<cdiv(N, 48), TB>>>(h1, Wl2, Wr2, xl2, xr2, N);

        // ---- layer 2 attention + gate + pool, fully fused (unroll-2) ----
        k_gat2_gate_pool<<<node_warp_blocks, TB>>>(rowptr, colsrc, xl2, xr2, att2, b2,
                                                   g1w, g1b, g2w, g2b, bat, gd, pool, N);

        k_head<<<G, 64>>>(pool, gd, l1w, l1b, l2w, l2b, out, C);
    } else {
        // ---- generic fallback (proven R5 path) ----
        k_init<<<cdiv((long long)N * HC1, TB), TB>>>(counts, gd, pool, O1, O2, d1, d2,
                                                     N, G, HC1, C, H);
        const int edge_warp_blocks = cdiv((long long)E * 32, TB);
        k_gemm<<<cdiv((long long)N * HC1, TB), TB>>>(x, Wl1, nullptr, xl1, N, IN, HC1, 0);
        k_gemm<<<cdiv((long long)N * HC1, TB), TB>>>(x, Wr1, nullptr, xr1, N, IN, HC1, 0);
        k_score<<<edge_warp_blocks, TB>>>(src, dst, xl1, xr1, att1, ex1, d1, E, H, C, HC1);
        k_agg<<<edge_warp_blocks, TB>>>(src, dst, xl1, ex1, d1, O1, E, H, C, HC1);
        k_relu_bias<<<cdiv((long long)N * HC1, TB), TB>>>(O1, b1, h1, N * HC1, HC1);

        k_gemm<<<cdiv((long long)N * C, TB), TB>>>(h1, Wl2, nullptr, xl2, N, HC1, C, 0);
        k_gemm<<<cdiv((long long)N * C, TB), TB>>>(h1, Wr2, nullptr, xr2, N, HC1, C, 0);
        k_score<<<edge_warp_blocks, TB>>>(src, dst, xl2, xr2, att2, ex2, d2, E, 1, C, C);
        k_agg<<<edge_warp_blocks, TB>>>(src, dst, xl2, ex2, d2, O2, E, 1, C, C);
        k_relu_bias<<<cdiv((long long)N * C, TB), TB>>>(O2, b2, h2, N * C, C);

        k_gemm<<<cdiv((long long)N * C, TB), TB>>>(h2, g1w, g1b, tmp, N, C, C, 1);
        k_gate2<<<node_warp_blocks, TB>>>(tmp, g2w, g2b, bat, gate, gd, N, C);
        k_pool<<<node_warp_blocks, TB>>>(bat, gate, gd, h2, pool, N, C);

        k_head<<<G, 64>>>(pool, nullptr, l1w, l1b, l2w, l2b, out, C);
    }
}